// round 4
// baseline (speedup 1.0000x reference)
#include <cuda_runtime.h>

// DynamicGraphModule_15144054686343
//
// Reference math reduces analytically:
//   scores[i,j] = row_term[i] + col_term[j] + b   (rank-1 + const)
//   adj = where(corr > 1.5, corr, 0)   -> elements in {0} U (1.5, inf)
//   adj = where(adj < -1.5, adj, 0)    -> identically ZERO
//   out = adj @ (e @ W_gcn) + b_gcn    == broadcast(b_gcn) exactly
//
// Kernel: broadcast b_gcn [512] into out [1, 4096, 512] (8 MB fp32 stores).
//
// R3: Blackwell 256-bit global ld/st (ld/st.global.v8.f32, sm_100+). One 32B
// bias load -> one 32B store per thread (depth-1 chain), 262144 threads,
// grid 1024 x 256. Halves STG warp-instruction count vs float4 (16384 -> 8192),
// minimizing the LSU-issue component; everything else is fixed launch cost.

static constexpr int ROW_VEC8 = 64;            // 512 floats per row = 64 x 32B
static constexpr int TOTAL_VEC8 = 4096 * 64;   // 262144 x 32B = 8 MB

__device__ __forceinline__ void ldg256(const void* p, float4& a, float4& b)
{
    asm volatile("ld.global.v8.f32 {%0,%1,%2,%3,%4,%5,%6,%7}, [%8];"
                 : "=f"(a.x), "=f"(a.y), "=f"(a.z), "=f"(a.w),
                   "=f"(b.x), "=f"(b.y), "=f"(b.z), "=f"(b.w)
                 : "l"(p));
}

__device__ __forceinline__ void stg256(void* p, const float4& a, const float4& b)
{
    asm volatile("st.global.v8.f32 [%0], {%1,%2,%3,%4,%5,%6,%7,%8};"
                 :: "l"(p),
                    "f"(a.x), "f"(a.y), "f"(a.z), "f"(a.w),
                    "f"(b.x), "f"(b.y), "f"(b.z), "f"(b.w)
                 : "memory");
}

__global__ void __launch_bounds__(256)
broadcast_bias_kernel(const float* __restrict__ bias,
                      float* __restrict__ out)
{
    const int idx = blockIdx.x * blockDim.x + threadIdx.x;   // 0..262143

    float4 a, b;
    ldg256(bias + (idx & (ROW_VEC8 - 1)) * 8, a, b);   // 32B-aligned (base 256B-aligned)
    stg256(out + (size_t)idx * 8, a, b);               // one 256-bit coalesced store
}

extern "C" void kernel_launch(void* const* d_in, const int* in_sizes, int n_in,
                              void* d_out, int out_size)
{
    // metadata order:
    // 0 spans_embeddings, 1 W_c1, 2 b_c1, 3 W_c2, 4 b_c2,
    // 5 W_link, 6 b_link, 7 W_gcn, 8 b_gcn
    const float* bias = (const float*)d_in[8];
    float* out = (float*)d_out;
    (void)in_sizes; (void)n_in; (void)out_size;   // out_size = 4096*512 exactly

    broadcast_bias_kernel<<<TOTAL_VEC8 / 256, 256>>>(bias, out);
}